// round 1
// baseline (speedup 1.0000x reference)
#include <cuda_runtime.h>
#include <cstdint>

#define C_DIM 128
#define L_DIM 24
#define HW_DIM 4096
#define B_DIM 4
#define R_DIM 64
#define TS 128          // spatial tile per CTA
#define XS_STRIDE 132   // padded row stride (floats) for x/h tile in smem

// Precomputed operands (written by precompute_kernel each launch; deterministic)
__device__ float g_Mt[C_DIM * C_DIM];   // Mt[k][c] = (U@V)[c][k]
__device__ float g_Wt[C_DIM * C_DIM];   // Wt[k][c] = Wout[c][k]
__device__ float g_sp[C_DIM];           // softplus(lam)

// ---------- packed f32x2 helpers ----------
__device__ __forceinline__ unsigned long long f2pack(float lo, float hi) {
    unsigned long long r;
    asm("mov.b64 %0, {%1, %2};" : "=l"(r) : "f"(lo), "f"(hi));
    return r;
}
__device__ __forceinline__ void f2unpack(unsigned long long v, float& lo, float& hi) {
    asm("mov.b64 {%0, %1}, %2;" : "=f"(lo), "=f"(hi) : "l"(v));
}
__device__ __forceinline__ unsigned long long f2fma(unsigned long long a,
                                                    unsigned long long b,
                                                    unsigned long long c) {
    unsigned long long d;
    asm("fma.rn.f32x2 %0, %1, %2, %3;" : "=l"(d) : "l"(a), "l"(b), "l"(c));
    return d;
}

// ---------- precompute: M = U@V (transposed), Wout^T, softplus(lam) ----------
__global__ void precompute_kernel(const float* __restrict__ lam,
                                  const float* __restrict__ U,
                                  const float* __restrict__ V,
                                  const float* __restrict__ Wout) {
    int tid = threadIdx.x;
    if (blockIdx.x == 0 && tid < C_DIM) {
        g_sp[tid] = log1pf(expf(lam[tid]));
    }
    int e = blockIdx.x * blockDim.x + tid;   // 64 blocks * 256 threads = 16384
    if (e < C_DIM * C_DIM) {
        int k = e / C_DIM;
        int c = e % C_DIM;
        float s0 = 0.f, s1 = 0.f, s2 = 0.f, s3 = 0.f;
        #pragma unroll 4
        for (int r = 0; r < R_DIM; r += 4) {
            s0 += U[c * R_DIM + r + 0] * V[(r + 0) * C_DIM + k];
            s1 += U[c * R_DIM + r + 1] * V[(r + 1) * C_DIM + k];
            s2 += U[c * R_DIM + r + 2] * V[(r + 2) * C_DIM + k];
            s3 += U[c * R_DIM + r + 3] * V[(r + 3) * C_DIM + k];
        }
        g_Mt[e] = (s0 + s1) + (s2 + s3);       // Mt[k][c]
        g_Wt[e] = Wout[c * C_DIM + k];         // Wt[k][c]
    }
}

// ---------- GEMM micro-tile: acc[8c][4 s-pairs] += A[k][c-tile] * B[k][s-tile] ----------
__device__ __forceinline__ void gemm_tile(const float* __restrict__ A,   // [128][128], k-major rows
                                          const float* __restrict__ Bm,  // [128][XS_STRIDE]
                                          int tc, int ts,
                                          unsigned long long acc[8][4]) {
    #pragma unroll 4
    for (int k = 0; k < C_DIM; ++k) {
        float4 a0 = *(const float4*)&A[k * C_DIM + tc];
        float4 a1 = *(const float4*)&A[k * C_DIM + tc + 4];
        float4 b0 = *(const float4*)&Bm[k * XS_STRIDE + ts];
        float4 b1 = *(const float4*)&Bm[k * XS_STRIDE + ts + 4];
        unsigned long long bb0 = f2pack(b0.x, b0.y);
        unsigned long long bb1 = f2pack(b0.z, b0.w);
        unsigned long long bb2 = f2pack(b1.x, b1.y);
        unsigned long long bb3 = f2pack(b1.z, b1.w);
        float av[8] = {a0.x, a0.y, a0.z, a0.w, a1.x, a1.y, a1.z, a1.w};
        #pragma unroll
        for (int i = 0; i < 8; ++i) {
            unsigned long long aa = f2pack(av[i], av[i]);
            acc[i][0] = f2fma(aa, bb0, acc[i][0]);
            acc[i][1] = f2fma(aa, bb1, acc[i][1]);
            acc[i][2] = f2fma(aa, bb2, acc[i][2]);
            acc[i][3] = f2fma(aa, bb3, acc[i][3]);
        }
    }
}

// ---------- main persistent kernel: one CTA = (batch, 128-spatial tile), loops t ----------
__global__ __launch_bounds__(256, 1)
void recurrent_kernel(const float* __restrict__ x,
                      const float* __restrict__ h0,
                      const float* __restrict__ listT,
                      float* __restrict__ out,
                      float* __restrict__ hfin) {
    extern __shared__ float smem[];
    float* sMt = smem;                 // 16384 floats
    float* sWt = smem + 16384;         // 16384 floats
    float* xs  = smem + 32768;         // 128 * 132 floats (x tile, reused as h tile)

    const int tid = threadIdx.x;
    const int b   = blockIdx.x >> 5;           // 32 tiles per batch
    const int s0  = (blockIdx.x & 31) * TS;
    const int tc  = (tid >> 4) * 8;            // channel micro-tile base
    const int ts  = (tid & 15) * 8;            // spatial micro-tile base

    // stage M^T and Wout^T into smem
    for (int i = tid * 4; i < C_DIM * C_DIM; i += 256 * 4) {
        *(float4*)&sMt[i] = *(const float4*)&g_Mt[i];
        *(float4*)&sWt[i] = *(const float4*)&g_Wt[i];
    }

    // load h tile into registers
    float h[8][8];
    #pragma unroll
    for (int i = 0; i < 8; ++i) {
        const float* p = h0 + (b * C_DIM + tc + i) * HW_DIM + s0 + ts;
        *(float4*)&h[i][0] = *(const float4*)p;
        *(float4*)&h[i][4] = *(const float4*)(p + 4);
    }

    float spc[8];
    #pragma unroll
    for (int i = 0; i < 8; ++i) spc[i] = g_sp[tc + i];

    const int f  = tid & 31;   // float4 index within a 128-float row
    const int r0 = tid >> 5;   // row group 0..7

    #pragma unroll 1
    for (int t = 0; t < L_DIM; ++t) {
        float dt = __ldg(&listT[b * L_DIM + t]);

        __syncthreads();  // previous GEMM2 done reading xs
        // load x tile: xs[k][s] = x[b, k, t, s0+s]
        #pragma unroll
        for (int it = 0; it < 16; ++it) {
            int k = it * 8 + r0;
            const float4* src =
                (const float4*)(x + ((b * C_DIM + k) * L_DIM + t) * HW_DIM + s0) + f;
            *(float4*)&xs[k * XS_STRIDE + f * 4] = *src;
        }
        __syncthreads();

        // GEMM1: u = M @ x_tile
        unsigned long long acc[8][4];
        #pragma unroll
        for (int i = 0; i < 8; ++i)
            #pragma unroll
            for (int j = 0; j < 4; ++j) acc[i][j] = 0ULL;
        gemm_tile(sMt, xs, tc, ts, acc);

        // h = exp(-softplus(lam)*dt) * h + u
        #pragma unroll
        for (int i = 0; i < 8; ++i) {
            float a = expf(-spc[i] * dt);
            #pragma unroll
            for (int j = 0; j < 4; ++j) {
                float u0, u1;
                f2unpack(acc[i][j], u0, u1);
                h[i][2 * j + 0] = a * h[i][2 * j + 0] + u0;
                h[i][2 * j + 1] = a * h[i][2 * j + 1] + u1;
            }
        }

        // residual: init GEMM2 accumulators with x (read xs BEFORE overwrite)
        #pragma unroll
        for (int i = 0; i < 8; ++i) {
            float4 rA = *(const float4*)&xs[(tc + i) * XS_STRIDE + ts];
            float4 rB = *(const float4*)&xs[(tc + i) * XS_STRIDE + ts + 4];
            acc[i][0] = f2pack(rA.x, rA.y);
            acc[i][1] = f2pack(rA.z, rA.w);
            acc[i][2] = f2pack(rB.x, rB.y);
            acc[i][3] = f2pack(rB.z, rB.w);
        }
        __syncthreads();  // all reads of x tile done

        // stage h tile into xs buffer for GEMM2
        #pragma unroll
        for (int i = 0; i < 8; ++i) {
            *(float4*)&xs[(tc + i) * XS_STRIDE + ts]     = make_float4(h[i][0], h[i][1], h[i][2], h[i][3]);
            *(float4*)&xs[(tc + i) * XS_STRIDE + ts + 4] = make_float4(h[i][4], h[i][5], h[i][6], h[i][7]);
        }
        __syncthreads();

        // GEMM2: out = x + Wout @ h
        gemm_tile(sWt, xs, tc, ts, acc);

        // store output tile
        #pragma unroll
        for (int i = 0; i < 8; ++i) {
            float o[8];
            #pragma unroll
            for (int j = 0; j < 4; ++j) f2unpack(acc[i][j], o[2 * j], o[2 * j + 1]);
            float* dst = out + ((b * C_DIM + tc + i) * L_DIM + t) * HW_DIM + s0 + ts;
            *(float4*)dst       = make_float4(o[0], o[1], o[2], o[3]);
            *(float4*)(dst + 4) = make_float4(o[4], o[5], o[6], o[7]);
        }
    }

    // final hidden state
    #pragma unroll
    for (int i = 0; i < 8; ++i) {
        float* dst = hfin + (b * C_DIM + tc + i) * HW_DIM + s0 + ts;
        *(float4*)dst       = make_float4(h[i][0], h[i][1], h[i][2], h[i][3]);
        *(float4*)(dst + 4) = make_float4(h[i][4], h[i][5], h[i][6], h[i][7]);
    }
}

extern "C" void kernel_launch(void* const* d_in, const int* in_sizes, int n_in,
                              void* d_out, int out_size) {
    const float* x     = (const float*)d_in[0];
    const float* h0    = (const float*)d_in[1];
    const float* listT = (const float*)d_in[2];
    const float* lam   = (const float*)d_in[3];
    const float* U     = (const float*)d_in[4];
    const float* V     = (const float*)d_in[5];
    const float* Wout  = (const float*)d_in[6];

    float* out  = (float*)d_out;
    float* hfin = out + (size_t)B_DIM * C_DIM * L_DIM * HW_DIM;

    precompute_kernel<<<64, 256>>>(lam, U, V, Wout);

    const size_t smem_bytes = (size_t)(2 * C_DIM * C_DIM + C_DIM * XS_STRIDE) * sizeof(float);
    cudaFuncSetAttribute(recurrent_kernel,
                         cudaFuncAttributeMaxDynamicSharedMemorySize, (int)smem_bytes);
    recurrent_kernel<<<B_DIM * (HW_DIM / TS), 256, smem_bytes>>>(x, h0, listT, out, hfin);
}

// round 3
// speedup vs baseline: 2.0608x; 2.0608x over previous
#include <cuda_runtime.h>
#include <cuda_bf16.h>
#include <cstdint>

#define B_DIM 4
#define C_DIM 128
#define L_DIM 24
#define HW_DIM 4096

#define SK   136          // bf16 row stride in elements
#define ROWB (SK * 2)     // 272 bytes per 128-col row (odd multiple of 16B -> conflict-free)

// SMEM byte offsets: 4 stationary weight tiles + shared X/H tile (hi/lo)
#define SM_MHI 0
#define SM_MLO 34816
#define SM_WHI 69632
#define SM_WLO 104448
#define SM_BHI 139264
#define SM_BLO 174080
#define SMEM_BYTES 208896

__device__ __align__(16) float g_M[C_DIM * C_DIM];             // (U@V)[c][k]
__device__ __align__(16) float g_decay[B_DIM * L_DIM * C_DIM]; // exp(-softplus(lam)*dt)

// ---------------- helpers ----------------
__device__ __forceinline__ uint32_t smem_u32(const void* p) {
    uint32_t a;
    asm("{ .reg .u64 t; cvta.to.shared.u64 t, %1; cvt.u32.u64 %0, t; }" : "=r"(a) : "l"(p));
    return a;
}
__device__ __forceinline__ void ldsm4(uint32_t& r0, uint32_t& r1, uint32_t& r2, uint32_t& r3, uint32_t a) {
    asm volatile("ldmatrix.sync.aligned.m8n8.x4.shared.b16 {%0,%1,%2,%3}, [%4];"
                 : "=r"(r0), "=r"(r1), "=r"(r2), "=r"(r3) : "r"(a));
}
__device__ __forceinline__ void ldsm4t(uint32_t& r0, uint32_t& r1, uint32_t& r2, uint32_t& r3, uint32_t a) {
    asm volatile("ldmatrix.sync.aligned.m8n8.x4.trans.shared.b16 {%0,%1,%2,%3}, [%4];"
                 : "=r"(r0), "=r"(r1), "=r"(r2), "=r"(r3) : "r"(a));
}
__device__ __forceinline__ void mma16816(float* d, const uint32_t* a, const uint32_t* b) {
    asm volatile("mma.sync.aligned.m16n8k16.row.col.f32.bf16.bf16.f32 "
                 "{%0,%1,%2,%3}, {%4,%5,%6,%7}, {%8,%9}, {%0,%1,%2,%3};"
                 : "+f"(d[0]), "+f"(d[1]), "+f"(d[2]), "+f"(d[3])
                 : "r"(a[0]), "r"(a[1]), "r"(a[2]), "r"(a[3]), "r"(b[0]), "r"(b[1]));
}
// fp32 pair -> bf16x2 hi + bf16x2 residual(lo); low 16 bits = first element
__device__ __forceinline__ void split2(float x0, float x1, uint32_t& hi, uint32_t& lo) {
    asm("cvt.rn.bf16x2.f32 %0, %1, %2;" : "=r"(hi) : "f"(x1), "f"(x0));
    float r0 = x0 - __uint_as_float(hi << 16);
    float r1 = x1 - __uint_as_float(hi & 0xffff0000u);
    asm("cvt.rn.bf16x2.f32 %0, %1, %2;" : "=r"(lo) : "f"(r1), "f"(r0));
}

// ---------------- precompute ----------------
__global__ void precompute_kernel(const float* __restrict__ lam,
                                  const float* __restrict__ U,
                                  const float* __restrict__ V,
                                  const float* __restrict__ listT) {
    int tid = threadIdx.x;
    if (blockIdx.x < 64) {
        int e = blockIdx.x * 256 + tid;
        int c = e >> 7, k = e & 127;
        float s0 = 0.f, s1 = 0.f;
        #pragma unroll 8
        for (int r = 0; r < 64; r += 2) {
            s0 += U[c * 64 + r] * V[r * C_DIM + k];
            s1 += U[c * 64 + r + 1] * V[(r + 1) * C_DIM + k];
        }
        g_M[e] = s0 + s1;
    } else {
        int idx = (blockIdx.x - 64) * 256 + tid;
        if (idx < B_DIM * L_DIM * C_DIM) {
            int c = idx & 127;
            int t = (idx >> 7) % L_DIM;
            int b = idx / (L_DIM * C_DIM);
            float sp = log1pf(expf(lam[c]));
            g_decay[idx] = expf(-sp * listT[b * L_DIM + t]);
        }
    }
}

// 3-pass bf16-split GEMM over k=128: acc[2][8][4] += A[m0..m0+31][k] * B[k][n0..n0+63]
__device__ __forceinline__ void gemm128(uint32_t aHi, uint32_t aLo,
                                        uint32_t bHi, uint32_t bLo,
                                        int m0, int n0, int lane,
                                        float acc[2][8][4]) {
    const int arow = lane & 15;
    const int aq   = lane >> 4;
    const uint32_t aDelta = aLo - aHi;
    const uint32_t bDelta = bLo - bHi;
    #pragma unroll
    for (int k = 0; k < 128; k += 16) {
        uint32_t ah[2][4], al[2][4];
        #pragma unroll
        for (int mt = 0; mt < 2; ++mt) {
            uint32_t addr = aHi + (uint32_t)((m0 + mt * 16 + arow) * ROWB + k * 2 + aq * 16);
            ldsm4(ah[mt][0], ah[mt][1], ah[mt][2], ah[mt][3], addr);
            ldsm4(al[mt][0], al[mt][1], al[mt][2], al[mt][3], addr + aDelta);
        }
        #pragma unroll
        for (int ng = 0; ng < 4; ++ng) {
            uint32_t addr = bHi + (uint32_t)((k + arow) * ROWB + (n0 + ng * 16) * 2 + aq * 16);
            uint32_t bh[4], bl[4];
            ldsm4t(bh[0], bh[1], bh[2], bh[3], addr);
            ldsm4t(bl[0], bl[1], bl[2], bl[3], addr + bDelta);
            #pragma unroll
            for (int hh = 0; hh < 2; ++hh) {
                const int nt = ng * 2 + hh;
                #pragma unroll
                for (int mt = 0; mt < 2; ++mt) {
                    mma16816(acc[mt][nt], ah[mt], bh + hh * 2);   // hi * hi
                    mma16816(acc[mt][nt], al[mt], bh + hh * 2);   // lo * hi
                    mma16816(acc[mt][nt], ah[mt], bl + hh * 2);   // hi * lo
                }
            }
        }
    }
}

// ---------------- main kernel ----------------
__global__ __launch_bounds__(256, 1)
void recurrent_kernel(const float* __restrict__ x,
                      const float* __restrict__ h0,
                      const float* __restrict__ Wout,
                      float* __restrict__ out,
                      float* __restrict__ hfin) {
    extern __shared__ char smem[];
    const uint32_t sb = smem_u32(smem);

    const int tid  = threadIdx.x;
    const int lane = tid & 31;
    const int wid  = tid >> 5;
    const int b    = blockIdx.x >> 5;
    const int s0   = (blockIdx.x & 31) * 128;
    const int wm   = wid & 3;            // 4 warps along c
    const int wn   = wid >> 2;           // 2 warps along s
    const int m0   = wm * 32;
    const int n0   = wn * 64;
    const int g    = lane >> 2;
    const int tq   = lane & 3;
    const size_t rstride = (size_t)L_DIM * HW_DIM;   // row step in x/out

    // ---- stationary weights: bf16-split into SMEM ----
    for (int e = tid; e < C_DIM * C_DIM; e += 256) {
        int r = e >> 7, k = e & 127;
        uint32_t off = (uint32_t)(r * ROWB + k * 2);
        float m = g_M[e];
        __nv_bfloat16 mh = __float2bfloat16_rn(m);
        __nv_bfloat16 ml = __float2bfloat16_rn(m - __bfloat162float(mh));
        *(__nv_bfloat16*)(smem + SM_MHI + off) = mh;
        *(__nv_bfloat16*)(smem + SM_MLO + off) = ml;
        float w = Wout[e];
        __nv_bfloat16 wh = __float2bfloat16_rn(w);
        __nv_bfloat16 wl = __float2bfloat16_rn(w - __bfloat162float(wh));
        *(__nv_bfloat16*)(smem + SM_WHI + off) = wh;
        *(__nv_bfloat16*)(smem + SM_WLO + off) = wl;
    }

    // ---- initial hidden state into accumulator-layout fragments ----
    float h[2][8][4];
    #pragma unroll
    for (int mt = 0; mt < 2; ++mt) {
        #pragma unroll
        for (int nt = 0; nt < 8; ++nt) {
            int c_lo = m0 + mt * 16 + g;
            int s    = s0 + n0 + nt * 8 + tq * 2;
            float2 v0 = *(const float2*)&h0[(size_t)(b * C_DIM + c_lo) * HW_DIM + s];
            float2 v1 = *(const float2*)&h0[(size_t)(b * C_DIM + c_lo + 8) * HW_DIM + s];
            h[mt][nt][0] = v0.x; h[mt][nt][1] = v0.y;
            h[mt][nt][2] = v1.x; h[mt][nt][3] = v1.y;
        }
    }

    __syncthreads();  // weights ready

    for (int t = 0; t < L_DIM; ++t) {
        // ---- stage x(t): fp32 -> bf16 hi/lo into B buffers ----
        __syncthreads();   // previous GEMM2 done reading B buffers
        #pragma unroll
        for (int it = 0; it < 16; ++it) {
            int idx = it * 256 + tid;
            int r   = idx >> 5;
            int c4  = idx & 31;
            float4 v = *(const float4*)(x + ((size_t)(b * C_DIM + r) * L_DIM + t) * HW_DIM
                                          + s0 + c4 * 4);
            uint32_t h0p, l0p, h1p, l1p;
            split2(v.x, v.y, h0p, l0p);
            split2(v.z, v.w, h1p, l1p);
            uint32_t off = (uint32_t)(r * ROWB + c4 * 8);
            *(uint2*)(smem + SM_BHI + off) = make_uint2(h0p, h1p);
            *(uint2*)(smem + SM_BLO + off) = make_uint2(l0p, l1p);
        }
        __syncthreads();

        // ---- GEMM1: u = M @ x ----
        float acc[2][8][4];
        #pragma unroll
        for (int mt = 0; mt < 2; ++mt)
            #pragma unroll
            for (int nt = 0; nt < 8; ++nt)
                #pragma unroll
                for (int q = 0; q < 4; ++q) acc[mt][nt][q] = 0.f;
        gemm128(sb + SM_MHI, sb + SM_MLO, sb + SM_BHI, sb + SM_BLO, m0, n0, lane, acc);

        // ---- recurrence: h = decay(c)*h + u ----
        {
            const float* dk = &g_decay[(b * L_DIM + t) * C_DIM];
            float d00 = __ldg(&dk[m0 + g]);
            float d08 = __ldg(&dk[m0 + 8 + g]);
            float d10 = __ldg(&dk[m0 + 16 + g]);
            float d18 = __ldg(&dk[m0 + 24 + g]);
            #pragma unroll
            for (int nt = 0; nt < 8; ++nt) {
                h[0][nt][0] = d00 * h[0][nt][0] + acc[0][nt][0];
                h[0][nt][1] = d00 * h[0][nt][1] + acc[0][nt][1];
                h[0][nt][2] = d08 * h[0][nt][2] + acc[0][nt][2];
                h[0][nt][3] = d08 * h[0][nt][3] + acc[0][nt][3];
                h[1][nt][0] = d10 * h[1][nt][0] + acc[1][nt][0];
                h[1][nt][1] = d10 * h[1][nt][1] + acc[1][nt][1];
                h[1][nt][2] = d18 * h[1][nt][2] + acc[1][nt][2];
                h[1][nt][3] = d18 * h[1][nt][3] + acc[1][nt][3];
            }
        }

        // ---- residual preload into GEMM2 accumulators (gmem, L2-hot) ----
        #pragma unroll
        for (int mt = 0; mt < 2; ++mt) {
            #pragma unroll
            for (int nt = 0; nt < 8; ++nt) {
                int d_lo = m0 + mt * 16 + g;
                const float* px = x + ((size_t)(b * C_DIM + d_lo) * L_DIM + t) * HW_DIM
                                    + s0 + n0 + nt * 8 + tq * 2;
                float2 r0 = *(const float2*)px;
                float2 r1 = *(const float2*)(px + 8 * rstride);
                acc[mt][nt][0] = r0.x; acc[mt][nt][1] = r0.y;
                acc[mt][nt][2] = r1.x; acc[mt][nt][3] = r1.y;
            }
        }

        __syncthreads();   // all warps finished reading x tile from B buffers

        // ---- write h (bf16 hi/lo) into B buffers for GEMM2 ----
        #pragma unroll
        for (int mt = 0; mt < 2; ++mt) {
            #pragma unroll
            for (int nt = 0; nt < 8; ++nt) {
                int c_lo = m0 + mt * 16 + g;
                int scol = n0 + nt * 8 + tq * 2;
                uint32_t hi0, lo0, hi1, lo1;
                split2(h[mt][nt][0], h[mt][nt][1], hi0, lo0);
                split2(h[mt][nt][2], h[mt][nt][3], hi1, lo1);
                uint32_t off0 = (uint32_t)(c_lo * ROWB + scol * 2);
                uint32_t off1 = (uint32_t)((c_lo + 8) * ROWB + scol * 2);
                *(uint32_t*)(smem + SM_BHI + off0) = hi0;
                *(uint32_t*)(smem + SM_BLO + off0) = lo0;
                *(uint32_t*)(smem + SM_BHI + off1) = hi1;
                *(uint32_t*)(smem + SM_BLO + off1) = lo1;
            }
        }
        __syncthreads();

        // ---- GEMM2: out = x + Wout @ h ----
        gemm128(sb + SM_WHI, sb + SM_WLO, sb + SM_BHI, sb + SM_BLO, m0, n0, lane, acc);

        // ---- store output ----
        #pragma unroll
        for (int mt = 0; mt < 2; ++mt) {
            #pragma unroll
            for (int nt = 0; nt < 8; ++nt) {
                int d_lo = m0 + mt * 16 + g;
                float* po = out + ((size_t)(b * C_DIM + d_lo) * L_DIM + t) * HW_DIM
                                + s0 + n0 + nt * 8 + tq * 2;
                *(float2*)po = make_float2(acc[mt][nt][0], acc[mt][nt][1]);
                *(float2*)(po + 8 * rstride) = make_float2(acc[mt][nt][2], acc[mt][nt][3]);
            }
        }
    }

    // ---- final hidden state ----
    #pragma unroll
    for (int mt = 0; mt < 2; ++mt) {
        #pragma unroll
        for (int nt = 0; nt < 8; ++nt) {
            int c_lo = m0 + mt * 16 + g;
            int s    = s0 + n0 + nt * 8 + tq * 2;
            *(float2*)&hfin[(size_t)(b * C_DIM + c_lo) * HW_DIM + s] =
                make_float2(h[mt][nt][0], h[mt][nt][1]);
            *(float2*)&hfin[(size_t)(b * C_DIM + c_lo + 8) * HW_DIM + s] =
                make_float2(h[mt][nt][2], h[mt][nt][3]);
        }
    }
}

extern "C" void kernel_launch(void* const* d_in, const int* in_sizes, int n_in,
                              void* d_out, int out_size) {
    const float* x     = (const float*)d_in[0];
    const float* h0    = (const float*)d_in[1];
    const float* listT = (const float*)d_in[2];
    const float* lam   = (const float*)d_in[3];
    const float* U     = (const float*)d_in[4];
    const float* V     = (const float*)d_in[5];
    const float* Wout  = (const float*)d_in[6];

    float* out  = (float*)d_out;
    float* hfin = out + (size_t)B_DIM * C_DIM * L_DIM * HW_DIM;

    precompute_kernel<<<112, 256>>>(lam, U, V, listT);

    cudaFuncSetAttribute(recurrent_kernel,
                         cudaFuncAttributeMaxDynamicSharedMemorySize, SMEM_BYTES);
    recurrent_kernel<<<B_DIM * (HW_DIM / 128), 256, SMEM_BYTES>>>(x, h0, Wout, out, hfin);
}

// round 4
// speedup vs baseline: 2.2898x; 1.1111x over previous
#include <cuda_runtime.h>
#include <cuda_bf16.h>
#include <cstdint>

#define B_DIM 4
#define C_DIM 128
#define L_DIM 24
#define HW_DIM 4096

#define SK   136          // bf16 row stride in elements
#define ROWB (SK * 2)     // 272 bytes/row: conflict-free for ldmatrix & scalar access

#define SM_MHI 0
#define SM_MLO 34816
#define SM_WHI 69632
#define SM_WLO 104448
#define SM_BHI 139264
#define SM_BLO 174080
#define SMEM_BYTES 208896

#define NTHREADS 512

__device__ __align__(16) float g_M[C_DIM * C_DIM];             // (U@V)[c][k]
__device__ __align__(16) float g_decay[B_DIM * L_DIM * C_DIM]; // exp(-softplus(lam)*dt)

// ---------------- helpers ----------------
__device__ __forceinline__ uint32_t smem_u32(const void* p) {
    uint32_t a;
    asm("{ .reg .u64 t; cvta.to.shared.u64 t, %1; cvt.u32.u64 %0, t; }" : "=r"(a) : "l"(p));
    return a;
}
__device__ __forceinline__ void ldsm4(uint32_t& r0, uint32_t& r1, uint32_t& r2, uint32_t& r3, uint32_t a) {
    asm volatile("ldmatrix.sync.aligned.m8n8.x4.shared.b16 {%0,%1,%2,%3}, [%4];"
                 : "=r"(r0), "=r"(r1), "=r"(r2), "=r"(r3) : "r"(a));
}
__device__ __forceinline__ void ldsm4t(uint32_t& r0, uint32_t& r1, uint32_t& r2, uint32_t& r3, uint32_t a) {
    asm volatile("ldmatrix.sync.aligned.m8n8.x4.trans.shared.b16 {%0,%1,%2,%3}, [%4];"
                 : "=r"(r0), "=r"(r1), "=r"(r2), "=r"(r3) : "r"(a));
}
__device__ __forceinline__ void mma16816(float* d, const uint32_t* a, const uint32_t* b) {
    asm volatile("mma.sync.aligned.m16n8k16.row.col.f32.bf16.bf16.f32 "
                 "{%0,%1,%2,%3}, {%4,%5,%6,%7}, {%8,%9}, {%0,%1,%2,%3};"
                 : "+f"(d[0]), "+f"(d[1]), "+f"(d[2]), "+f"(d[3])
                 : "r"(a[0]), "r"(a[1]), "r"(a[2]), "r"(a[3]), "r"(b[0]), "r"(b[1]));
}
__device__ __forceinline__ void split2(float x0, float x1, uint32_t& hi, uint32_t& lo) {
    asm("cvt.rn.bf16x2.f32 %0, %1, %2;" : "=r"(hi) : "f"(x1), "f"(x0));
    float r0 = x0 - __uint_as_float(hi << 16);
    float r1 = x1 - __uint_as_float(hi & 0xffff0000u);
    asm("cvt.rn.bf16x2.f32 %0, %1, %2;" : "=r"(lo) : "f"(r1), "f"(r0));
}
__device__ __forceinline__ float2 join2(uint32_t hi, uint32_t lo) {
    float a = __uint_as_float(hi << 16) + __uint_as_float(lo << 16);
    float b = __uint_as_float(hi & 0xffff0000u) + __uint_as_float(lo & 0xffff0000u);
    return make_float2(a, b);
}

// ---------------- precompute ----------------
__global__ void precompute_kernel(const float* __restrict__ lam,
                                  const float* __restrict__ U,
                                  const float* __restrict__ V,
                                  const float* __restrict__ listT) {
    int tid = threadIdx.x;
    if (blockIdx.x < 64) {
        int e = blockIdx.x * 256 + tid;
        int c = e >> 7, k = e & 127;
        float s0 = 0.f, s1 = 0.f;
        #pragma unroll 8
        for (int r = 0; r < 64; r += 2) {
            s0 += U[c * 64 + r] * V[r * C_DIM + k];
            s1 += U[c * 64 + r + 1] * V[(r + 1) * C_DIM + k];
        }
        g_M[e] = s0 + s1;
    } else {
        int idx = (blockIdx.x - 64) * 256 + tid;
        if (idx < B_DIM * L_DIM * C_DIM) {
            int c = idx & 127;
            int t = (idx >> 7) % L_DIM;
            int b = idx / (L_DIM * C_DIM);
            float sp = log1pf(expf(lam[c]));
            g_decay[idx] = expf(-sp * listT[b * L_DIM + t]);
        }
    }
}

// 3-pass bf16-split GEMM: acc[2][4][4] += A[m0..+32][k] * B[k][n0..+32], k=128
__device__ __forceinline__ void gemm128(uint32_t aHi, uint32_t aLo,
                                        uint32_t bHi, uint32_t bLo,
                                        int m0, int n0, int lane,
                                        float acc[2][4][4]) {
    const int arow = lane & 15;
    const int aq   = lane >> 4;
    const uint32_t aD = aLo - aHi;
    const uint32_t bD = bLo - bHi;
    #pragma unroll
    for (int k = 0; k < 128; k += 16) {
        uint32_t ah[2][4], al[2][4];
        #pragma unroll
        for (int mt = 0; mt < 2; ++mt) {
            uint32_t addr = aHi + (uint32_t)((m0 + mt * 16 + arow) * ROWB + k * 2 + aq * 16);
            ldsm4(ah[mt][0], ah[mt][1], ah[mt][2], ah[mt][3], addr);
            ldsm4(al[mt][0], al[mt][1], al[mt][2], al[mt][3], addr + aD);
        }
        #pragma unroll
        for (int ng = 0; ng < 2; ++ng) {
            uint32_t addr = bHi + (uint32_t)((k + arow) * ROWB + (n0 + ng * 16) * 2 + aq * 16);
            uint32_t bh[4], bl[4];
            ldsm4t(bh[0], bh[1], bh[2], bh[3], addr);
            ldsm4t(bl[0], bl[1], bl[2], bl[3], addr + bD);
            #pragma unroll
            for (int hh = 0; hh < 2; ++hh) {
                const int nt = ng * 2 + hh;
                #pragma unroll
                for (int mt = 0; mt < 2; ++mt) {
                    mma16816(acc[mt][nt], ah[mt], bh + hh * 2);
                    mma16816(acc[mt][nt], al[mt], bh + hh * 2);
                    mma16816(acc[mt][nt], ah[mt], bl + hh * 2);
                }
            }
        }
    }
}

// ---------------- main kernel ----------------
__global__ __launch_bounds__(NTHREADS, 1)
void recurrent_kernel(const float* __restrict__ x,
                      const float* __restrict__ h0,
                      const float* __restrict__ Wout,
                      float* __restrict__ out,
                      float* __restrict__ hfin) {
    extern __shared__ char smem[];
    const uint32_t sb = smem_u32(smem);

    const int tid  = threadIdx.x;
    const int lane = tid & 31;
    const int wid  = tid >> 5;            // 0..15
    const int b    = blockIdx.x >> 5;
    const int s0   = (blockIdx.x & 31) * 128;
    const int wm   = wid & 3;             // 4 warps along c
    const int wn   = wid >> 2;            // 4 warps along s
    const int m0   = wm * 32;
    const int n0   = wn * 32;
    const int g    = lane >> 2;
    const int tq   = lane & 3;
    const size_t rstride = (size_t)L_DIM * HW_DIM;

    // ---- stationary weights: bf16-split into SMEM ----
    for (int e = tid; e < C_DIM * C_DIM; e += NTHREADS) {
        int r = e >> 7, k = e & 127;
        uint32_t off = (uint32_t)(r * ROWB + k * 2);
        float m = g_M[e];
        __nv_bfloat16 mh = __float2bfloat16_rn(m);
        __nv_bfloat16 ml = __float2bfloat16_rn(m - __bfloat162float(mh));
        *(__nv_bfloat16*)(smem + SM_MHI + off) = mh;
        *(__nv_bfloat16*)(smem + SM_MLO + off) = ml;
        float w = Wout[e];
        __nv_bfloat16 wh = __float2bfloat16_rn(w);
        __nv_bfloat16 wl = __float2bfloat16_rn(w - __bfloat162float(wh));
        *(__nv_bfloat16*)(smem + SM_WHI + off) = wh;
        *(__nv_bfloat16*)(smem + SM_WLO + off) = wl;
    }

    // ---- initial hidden state into accumulator-layout fragments ----
    float h[2][4][4];
    #pragma unroll
    for (int mt = 0; mt < 2; ++mt) {
        #pragma unroll
        for (int nt = 0; nt < 4; ++nt) {
            int c_lo = m0 + mt * 16 + g;
            int s    = s0 + n0 + nt * 8 + tq * 2;
            float2 v0 = *(const float2*)&h0[(size_t)(b * C_DIM + c_lo) * HW_DIM + s];
            float2 v1 = *(const float2*)&h0[(size_t)(b * C_DIM + c_lo + 8) * HW_DIM + s];
            h[mt][nt][0] = v0.x; h[mt][nt][1] = v0.y;
            h[mt][nt][2] = v1.x; h[mt][nt][3] = v1.y;
        }
    }

    __syncthreads();  // weights ready

    for (int t = 0; t < L_DIM; ++t) {
        // ---- stage x(t): fp32 -> bf16 hi/lo into B buffers ----
        __syncthreads();   // previous GEMM2 done reading B buffers
        #pragma unroll
        for (int it = 0; it < 8; ++it) {
            int idx = it * NTHREADS + tid;
            int r   = idx >> 5;
            int c4  = idx & 31;
            float4 v = *(const float4*)(x + ((size_t)(b * C_DIM + r) * L_DIM + t) * HW_DIM
                                          + s0 + c4 * 4);
            uint32_t h0p, l0p, h1p, l1p;
            split2(v.x, v.y, h0p, l0p);
            split2(v.z, v.w, h1p, l1p);
            uint32_t off = (uint32_t)(r * ROWB + c4 * 8);
            *(uint2*)(smem + SM_BHI + off) = make_uint2(h0p, h1p);
            *(uint2*)(smem + SM_BLO + off) = make_uint2(l0p, l1p);
        }
        __syncthreads();

        // ---- GEMM1: u = M @ x ----
        float acc[2][4][4];
        #pragma unroll
        for (int mt = 0; mt < 2; ++mt)
            #pragma unroll
            for (int nt = 0; nt < 4; ++nt)
                #pragma unroll
                for (int q = 0; q < 4; ++q) acc[mt][nt][q] = 0.f;
        gemm128(sb + SM_MHI, sb + SM_MLO, sb + SM_BHI, sb + SM_BLO, m0, n0, lane, acc);

        // ---- recurrence: h = decay(c)*h + u ----
        {
            const float* dk = &g_decay[(b * L_DIM + t) * C_DIM];
            #pragma unroll
            for (int mt = 0; mt < 2; ++mt) {
                float dA = __ldg(&dk[m0 + mt * 16 + g]);
                float dB = __ldg(&dk[m0 + mt * 16 + 8 + g]);
                #pragma unroll
                for (int nt = 0; nt < 4; ++nt) {
                    h[mt][nt][0] = dA * h[mt][nt][0] + acc[mt][nt][0];
                    h[mt][nt][1] = dA * h[mt][nt][1] + acc[mt][nt][1];
                    h[mt][nt][2] = dB * h[mt][nt][2] + acc[mt][nt][2];
                    h[mt][nt][3] = dB * h[mt][nt][3] + acc[mt][nt][3];
                }
            }
        }

        // ---- residual x from SMEM (hi+lo reconstruction; error ~2^-17) ----
        #pragma unroll
        for (int mt = 0; mt < 2; ++mt) {
            #pragma unroll
            for (int nt = 0; nt < 4; ++nt) {
                int c_lo = m0 + mt * 16 + g;
                uint32_t off0 = (uint32_t)(c_lo * ROWB + (n0 + nt * 8 + tq * 2) * 2);
                uint32_t off1 = off0 + 8 * ROWB;
                uint32_t xh0 = *(const uint32_t*)(smem + SM_BHI + off0);
                uint32_t xl0 = *(const uint32_t*)(smem + SM_BLO + off0);
                uint32_t xh1 = *(const uint32_t*)(smem + SM_BHI + off1);
                uint32_t xl1 = *(const uint32_t*)(smem + SM_BLO + off1);
                float2 r0 = join2(xh0, xl0);
                float2 r1 = join2(xh1, xl1);
                acc[mt][nt][0] = r0.x; acc[mt][nt][1] = r0.y;
                acc[mt][nt][2] = r1.x; acc[mt][nt][3] = r1.y;
            }
        }

        __syncthreads();   // all warps done reading x tile

        // ---- write h (bf16 hi/lo) into B buffers for GEMM2 ----
        #pragma unroll
        for (int mt = 0; mt < 2; ++mt) {
            #pragma unroll
            for (int nt = 0; nt < 4; ++nt) {
                int c_lo = m0 + mt * 16 + g;
                int scol = n0 + nt * 8 + tq * 2;
                uint32_t hi0, lo0, hi1, lo1;
                split2(h[mt][nt][0], h[mt][nt][1], hi0, lo0);
                split2(h[mt][nt][2], h[mt][nt][3], hi1, lo1);
                uint32_t off0 = (uint32_t)(c_lo * ROWB + scol * 2);
                uint32_t off1 = off0 + 8 * ROWB;
                *(uint32_t*)(smem + SM_BHI + off0) = hi0;
                *(uint32_t*)(smem + SM_BLO + off0) = lo0;
                *(uint32_t*)(smem + SM_BHI + off1) = hi1;
                *(uint32_t*)(smem + SM_BLO + off1) = lo1;
            }
        }
        __syncthreads();

        // ---- GEMM2: out = x + Wout @ h ----
        gemm128(sb + SM_WHI, sb + SM_WLO, sb + SM_BHI, sb + SM_BLO, m0, n0, lane, acc);

        // ---- store output ----
        #pragma unroll
        for (int mt = 0; mt < 2; ++mt) {
            #pragma unroll
            for (int nt = 0; nt < 4; ++nt) {
                int d_lo = m0 + mt * 16 + g;
                float* po = out + ((size_t)(b * C_DIM + d_lo) * L_DIM + t) * HW_DIM
                                + s0 + n0 + nt * 8 + tq * 2;
                *(float2*)po = make_float2(acc[mt][nt][0], acc[mt][nt][1]);
                *(float2*)(po + 8 * rstride) = make_float2(acc[mt][nt][2], acc[mt][nt][3]);
            }
        }
    }

    // ---- final hidden state ----
    #pragma unroll
    for (int mt = 0; mt < 2; ++mt) {
        #pragma unroll
        for (int nt = 0; nt < 4; ++nt) {
            int c_lo = m0 + mt * 16 + g;
            int s    = s0 + n0 + nt * 8 + tq * 2;
            *(float2*)&hfin[(size_t)(b * C_DIM + c_lo) * HW_DIM + s] =
                make_float2(h[mt][nt][0], h[mt][nt][1]);
            *(float2*)&hfin[(size_t)(b * C_DIM + c_lo + 8) * HW_DIM + s] =
                make_float2(h[mt][nt][2], h[mt][nt][3]);
        }
    }
}

extern "C" void kernel_launch(void* const* d_in, const int* in_sizes, int n_in,
                              void* d_out, int out_size) {
    const float* x     = (const float*)d_in[0];
    const float* h0    = (const float*)d_in[1];
    const float* listT = (const float*)d_in[2];
    const float* lam   = (const float*)d_in[3];
    const float* U     = (const float*)d_in[4];
    const float* V     = (const float*)d_in[5];
    const float* Wout  = (const float*)d_in[6];

    float* out  = (float*)d_out;
    float* hfin = out + (size_t)B_DIM * C_DIM * L_DIM * HW_DIM;

    precompute_kernel<<<112, 256>>>(lam, U, V, listT);

    cudaFuncSetAttribute(recurrent_kernel,
                         cudaFuncAttributeMaxDynamicSharedMemorySize, SMEM_BYTES);
    recurrent_kernel<<<B_DIM * (HW_DIM / 128), NTHREADS, SMEM_BYTES>>>(x, h0, Wout, out, hfin);
}

// round 5
// speedup vs baseline: 3.0143x; 1.3164x over previous
#include <cuda_runtime.h>
#include <cuda_fp16.h>
#include <cstdint>

#define B_DIM 4
#define C_DIM 128
#define L_DIM 24
#define HW_DIM 4096

#define SK   136          // fp16 row stride in elements
#define ROWB (SK * 2)     // 272 bytes/row

#define SM_MHI 0
#define SM_MLO 34816
#define SM_WHI 69632
#define SM_WLO 104448
#define SM_BHI 139264
#define SM_BLO 174080
#define SMEM_BYTES 208896

#define NTHREADS 512

__device__ __align__(16) float g_M[C_DIM * C_DIM];             // (U@V)[c][k]
__device__ __align__(16) float g_decay[B_DIM * L_DIM * C_DIM]; // exp(-softplus(lam)*dt)

// ---------------- helpers ----------------
__device__ __forceinline__ uint32_t smem_u32(const void* p) {
    uint32_t a;
    asm("{ .reg .u64 t; cvta.to.shared.u64 t, %1; cvt.u32.u64 %0, t; }" : "=r"(a) : "l"(p));
    return a;
}
__device__ __forceinline__ void ldsm4(uint32_t& r0, uint32_t& r1, uint32_t& r2, uint32_t& r3, uint32_t a) {
    asm volatile("ldmatrix.sync.aligned.m8n8.x4.shared.b16 {%0,%1,%2,%3}, [%4];"
                 : "=r"(r0), "=r"(r1), "=r"(r2), "=r"(r3) : "r"(a));
}
__device__ __forceinline__ void ldsm4t(uint32_t& r0, uint32_t& r1, uint32_t& r2, uint32_t& r3, uint32_t a) {
    asm volatile("ldmatrix.sync.aligned.m8n8.x4.trans.shared.b16 {%0,%1,%2,%3}, [%4];"
                 : "=r"(r0), "=r"(r1), "=r"(r2), "=r"(r3) : "r"(a));
}
__device__ __forceinline__ void mma16816(float* d, const uint32_t* a, const uint32_t* b) {
    asm volatile("mma.sync.aligned.m16n8k16.row.col.f32.f16.f16.f32 "
                 "{%0,%1,%2,%3}, {%4,%5,%6,%7}, {%8,%9}, {%0,%1,%2,%3};"
                 : "+f"(d[0]), "+f"(d[1]), "+f"(d[2]), "+f"(d[3])
                 : "r"(a[0]), "r"(a[1]), "r"(a[2]), "r"(a[3]), "r"(b[0]), "r"(b[1]));
}
// fp32 pair -> f16x2 hi + f16x2 residual(lo); low 16 bits = first element
__device__ __forceinline__ void split2h(float x0, float x1, uint32_t& hi, uint32_t& lo) {
    asm("cvt.rn.f16x2.f32 %0, %1, %2;" : "=r"(hi) : "f"(x1), "f"(x0));
    float2 hf = __half22float2(*reinterpret_cast<__half2*>(&hi));
    float r0 = x0 - hf.x;
    float r1 = x1 - hf.y;
    asm("cvt.rn.f16x2.f32 %0, %1, %2;" : "=r"(lo) : "f"(r1), "f"(r0));
}
__device__ __forceinline__ float2 join2h(uint32_t hi, uint32_t lo) {
    float2 a = __half22float2(*reinterpret_cast<__half2*>(&hi));
    float2 b = __half22float2(*reinterpret_cast<__half2*>(&lo));
    return make_float2(a.x + b.x, a.y + b.y);
}

// ---------------- precompute ----------------
__global__ void precompute_kernel(const float* __restrict__ lam,
                                  const float* __restrict__ U,
                                  const float* __restrict__ V,
                                  const float* __restrict__ listT) {
    int tid = threadIdx.x;
    if (blockIdx.x < 64) {
        int e = blockIdx.x * 256 + tid;
        int c = e >> 7, k = e & 127;
        float s0 = 0.f, s1 = 0.f;
        #pragma unroll 8
        for (int r = 0; r < 64; r += 2) {
            s0 += U[c * 64 + r] * V[r * C_DIM + k];
            s1 += U[c * 64 + r + 1] * V[(r + 1) * C_DIM + k];
        }
        g_M[e] = s0 + s1;
    } else {
        int idx = (blockIdx.x - 64) * 256 + tid;
        if (idx < B_DIM * L_DIM * C_DIM) {
            int c = idx & 127;
            int t = (idx >> 7) % L_DIM;
            int b = idx / (L_DIM * C_DIM);
            float sp = log1pf(expf(lam[c]));
            g_decay[idx] = expf(-sp * listT[b * L_DIM + t]);
        }
    }
}

// 2-pass fp16-split GEMM: acc[2][4][4] += (Ahi+Alo)[m0..+32][k] * Bhi[k][n0..+32], k=128
__device__ __forceinline__ void gemm128(uint32_t aHi, uint32_t aLo, uint32_t bHi,
                                        int m0, int n0, int lane,
                                        float acc[2][4][4]) {
    const int arow = lane & 15;
    const int aq   = lane >> 4;
    const uint32_t aD = aLo - aHi;
    #pragma unroll
    for (int k = 0; k < 128; k += 16) {
        uint32_t ah[2][4], al[2][4];
        #pragma unroll
        for (int mt = 0; mt < 2; ++mt) {
            uint32_t addr = aHi + (uint32_t)((m0 + mt * 16 + arow) * ROWB + k * 2 + aq * 16);
            ldsm4(ah[mt][0], ah[mt][1], ah[mt][2], ah[mt][3], addr);
            ldsm4(al[mt][0], al[mt][1], al[mt][2], al[mt][3], addr + aD);
        }
        #pragma unroll
        for (int ng = 0; ng < 2; ++ng) {
            uint32_t addr = bHi + (uint32_t)((k + arow) * ROWB + (n0 + ng * 16) * 2 + aq * 16);
            uint32_t bh[4];
            ldsm4t(bh[0], bh[1], bh[2], bh[3], addr);
            #pragma unroll
            for (int hh = 0; hh < 2; ++hh) {
                const int nt = ng * 2 + hh;
                #pragma unroll
                for (int mt = 0; mt < 2; ++mt) {
                    mma16816(acc[mt][nt], ah[mt], bh + hh * 2);
                    mma16816(acc[mt][nt], al[mt], bh + hh * 2);
                }
            }
        }
    }
}

// ---------------- main kernel ----------------
__global__ __launch_bounds__(NTHREADS, 1)
void recurrent_kernel(const float* __restrict__ x,
                      const float* __restrict__ h0,
                      const float* __restrict__ Wout,
                      float* __restrict__ out,
                      float* __restrict__ hfin) {
    extern __shared__ char smem[];
    const uint32_t sb = smem_u32(smem);

    const int tid  = threadIdx.x;
    const int lane = tid & 31;
    const int wid  = tid >> 5;            // 0..15
    const int b    = blockIdx.x >> 5;
    const int s0   = (blockIdx.x & 31) * 128;
    const int wm   = wid & 3;
    const int wn   = wid >> 2;
    const int m0   = wm * 32;
    const int n0   = wn * 32;
    const int g    = lane >> 2;
    const int tq   = lane & 3;
    const size_t rstride = (size_t)L_DIM * HW_DIM;

    // staging coordinates for this thread (8 chunks of float4)
    const int sr  = tid >> 5;       // base row (stride 16 across it)
    const int sc4 = tid & 31;       // float4 column

    // ---- stationary weights: fp16-split into SMEM ----
    for (int e = tid; e < C_DIM * C_DIM; e += NTHREADS) {
        int r = e >> 7, k = e & 127;
        uint32_t off = (uint32_t)(r * ROWB + k * 2);
        float m = g_M[e];
        __half mh = __float2half_rn(m);
        __half ml = __float2half_rn(m - __half2float(mh));
        *(__half*)(smem + SM_MHI + off) = mh;
        *(__half*)(smem + SM_MLO + off) = ml;
        float w = Wout[e];
        __half wh = __float2half_rn(w);
        __half wl = __float2half_rn(w - __half2float(wh));
        *(__half*)(smem + SM_WHI + off) = wh;
        *(__half*)(smem + SM_WLO + off) = wl;
    }

    // ---- initial hidden state into accumulator-layout fragments ----
    float h[2][4][4];
    #pragma unroll
    for (int mt = 0; mt < 2; ++mt) {
        #pragma unroll
        for (int nt = 0; nt < 4; ++nt) {
            int c_lo = m0 + mt * 16 + g;
            int s    = s0 + n0 + nt * 8 + tq * 2;
            float2 v0 = *(const float2*)&h0[(size_t)(b * C_DIM + c_lo) * HW_DIM + s];
            float2 v1 = *(const float2*)&h0[(size_t)(b * C_DIM + c_lo + 8) * HW_DIM + s];
            h[mt][nt][0] = v0.x; h[mt][nt][1] = v0.y;
            h[mt][nt][2] = v1.x; h[mt][nt][3] = v1.y;
        }
    }

    // ---- prefetch x(0) ----
    float4 xr[8];
    #pragma unroll
    for (int it = 0; it < 8; ++it) {
        int r = it * 16 + sr;
        xr[it] = *(const float4*)(x + ((size_t)(b * C_DIM + r) * L_DIM + 0) * HW_DIM
                                    + s0 + sc4 * 4);
    }

    __syncthreads();  // weights ready

    for (int t = 0; t < L_DIM; ++t) {
        // ---- stage x(t) from prefetch regs: fp32 -> f16 hi/lo ----
        // (entry sync of iteration t>0 is the post-h-write sync below; for t=0
        //  the weights sync above covers it)
        #pragma unroll
        for (int it = 0; it < 8; ++it) {
            int r = it * 16 + sr;
            float4 v = xr[it];
            uint32_t h0p, l0p, h1p, l1p;
            split2h(v.x, v.y, h0p, l0p);
            split2h(v.z, v.w, h1p, l1p);
            uint32_t off = (uint32_t)(r * ROWB + sc4 * 8);
            *(uint2*)(smem + SM_BHI + off) = make_uint2(h0p, h1p);
            *(uint2*)(smem + SM_BLO + off) = make_uint2(l0p, l1p);
        }
        __syncthreads();

        // ---- GEMM1: u = M @ x ----
        float acc[2][4][4];
        #pragma unroll
        for (int mt = 0; mt < 2; ++mt)
            #pragma unroll
            for (int nt = 0; nt < 4; ++nt)
                #pragma unroll
                for (int q = 0; q < 4; ++q) acc[mt][nt][q] = 0.f;
        gemm128(sb + SM_MHI, sb + SM_MLO, sb + SM_BHI, m0, n0, lane, acc);

        // ---- recurrence: h = decay(c)*h + u ----
        {
            const float* dk = &g_decay[(b * L_DIM + t) * C_DIM];
            #pragma unroll
            for (int mt = 0; mt < 2; ++mt) {
                float dA = __ldg(&dk[m0 + mt * 16 + g]);
                float dB = __ldg(&dk[m0 + mt * 16 + 8 + g]);
                #pragma unroll
                for (int nt = 0; nt < 4; ++nt) {
                    h[mt][nt][0] = dA * h[mt][nt][0] + acc[mt][nt][0];
                    h[mt][nt][1] = dA * h[mt][nt][1] + acc[mt][nt][1];
                    h[mt][nt][2] = dB * h[mt][nt][2] + acc[mt][nt][2];
                    h[mt][nt][3] = dB * h[mt][nt][3] + acc[mt][nt][3];
                }
            }
        }

        // ---- residual x from SMEM (hi+lo fp16 reconstruction) ----
        #pragma unroll
        for (int mt = 0; mt < 2; ++mt) {
            #pragma unroll
            for (int nt = 0; nt < 4; ++nt) {
                int c_lo = m0 + mt * 16 + g;
                uint32_t off0 = (uint32_t)(c_lo * ROWB + (n0 + nt * 8 + tq * 2) * 2);
                uint32_t off1 = off0 + 8 * ROWB;
                uint32_t xh0 = *(const uint32_t*)(smem + SM_BHI + off0);
                uint32_t xl0 = *(const uint32_t*)(smem + SM_BLO + off0);
                uint32_t xh1 = *(const uint32_t*)(smem + SM_BHI + off1);
                uint32_t xl1 = *(const uint32_t*)(smem + SM_BLO + off1);
                float2 r0 = join2h(xh0, xl0);
                float2 r1 = join2h(xh1, xl1);
                acc[mt][nt][0] = r0.x; acc[mt][nt][1] = r0.y;
                acc[mt][nt][2] = r1.x; acc[mt][nt][3] = r1.y;
            }
        }

        __syncthreads();   // all warps done reading x tile

        // ---- write h (f16 hi only) into B buffer for GEMM2 ----
        #pragma unroll
        for (int mt = 0; mt < 2; ++mt) {
            #pragma unroll
            for (int nt = 0; nt < 4; ++nt) {
                int c_lo = m0 + mt * 16 + g;
                int scol = n0 + nt * 8 + tq * 2;
                uint32_t hi0, lo0, hi1, lo1;
                split2h(h[mt][nt][0], h[mt][nt][1], hi0, lo0);
                split2h(h[mt][nt][2], h[mt][nt][3], hi1, lo1);
                (void)lo0; (void)lo1;
                uint32_t off0 = (uint32_t)(c_lo * ROWB + scol * 2);
                uint32_t off1 = off0 + 8 * ROWB;
                *(uint32_t*)(smem + SM_BHI + off0) = hi0;
                *(uint32_t*)(smem + SM_BHI + off1) = hi1;
            }
        }

        // ---- prefetch x(t+1) (hidden behind GEMM2) ----
        {
            int tn = (t + 1 < L_DIM) ? t + 1 : t;
            #pragma unroll
            for (int it = 0; it < 8; ++it) {
                int r = it * 16 + sr;
                xr[it] = *(const float4*)(x + ((size_t)(b * C_DIM + r) * L_DIM + tn) * HW_DIM
                                            + s0 + sc4 * 4);
            }
        }
        __syncthreads();

        // ---- GEMM2: out = x + Wout @ h ----
        gemm128(sb + SM_WHI, sb + SM_WLO, sb + SM_BHI, m0, n0, lane, acc);

        // ---- store output ----
        #pragma unroll
        for (int mt = 0; mt < 2; ++mt) {
            #pragma unroll
            for (int nt = 0; nt < 4; ++nt) {
                int d_lo = m0 + mt * 16 + g;
                float* po = out + ((size_t)(b * C_DIM + d_lo) * L_DIM + t) * HW_DIM
                                + s0 + n0 + nt * 8 + tq * 2;
                *(float2*)po = make_float2(acc[mt][nt][0], acc[mt][nt][1]);
                *(float2*)(po + 8 * rstride) = make_float2(acc[mt][nt][2], acc[mt][nt][3]);
            }
        }
        __syncthreads();   // GEMM2 reads of B done before next staging overwrites
    }

    // ---- final hidden state ----
    #pragma unroll
    for (int mt = 0; mt < 2; ++mt) {
        #pragma unroll
        for (int nt = 0; nt < 4; ++nt) {
            int c_lo = m0 + mt * 16 + g;
            int s    = s0 + n0 + nt * 8 + tq * 2;
            *(float2*)&hfin[(size_t)(b * C_DIM + c_lo) * HW_DIM + s] =
                make_float2(h[mt][nt][0], h[mt][nt][1]);
            *(float2*)&hfin[(size_t)(b * C_DIM + c_lo + 8) * HW_DIM + s] =
                make_float2(h[mt][nt][2], h[mt][nt][3]);
        }
    }
}

extern "C" void kernel_launch(void* const* d_in, const int* in_sizes, int n_in,
                              void* d_out, int out_size) {
    const float* x     = (const float*)d_in[0];
    const float* h0    = (const float*)d_in[1];
    const float* listT = (const float*)d_in[2];
    const float* lam   = (const float*)d_in[3];
    const float* U     = (const float*)d_in[4];
    const float* V     = (const float*)d_in[5];
    const float* Wout  = (const float*)d_in[6];

    float* out  = (float*)d_out;
    float* hfin = out + (size_t)B_DIM * C_DIM * L_DIM * HW_DIM;

    precompute_kernel<<<112, 256>>>(lam, U, V, listT);

    cudaFuncSetAttribute(recurrent_kernel,
                         cudaFuncAttributeMaxDynamicSharedMemorySize, SMEM_BYTES);
    recurrent_kernel<<<B_DIM * (HW_DIM / 128), NTHREADS, SMEM_BYTES>>>(x, h0, Wout, out, hfin);
}